// round 1
// baseline (speedup 1.0000x reference)
#include <cuda_runtime.h>

// Problem constants (mirror reference)
#define D0V 32
#define D1V 32
#define GV  1024            // D0*D1
#define KV  5               // n_orders
#define BSV 4               // batches (BS*NID)
#define NITER 16
#define WPEN 0.001f         // 1/DS
#define ALPHAP 0.1f

// Solves M x = b per batch via block-Jacobi:
//   M = B + E,  B = blockdiag of 5x5 node blocks (batch-0 coeffs),
//   E = weak (1e-3 scale) neighbor couplings from derivative constraints.
// rho(B^{-1}E) <= 0.082 guaranteed -> 16 iterations converge to fp32 limits.
__global__ __launch_bounds__(1024, 1)
void pde_blockjacobi_kernel(const float* __restrict__ coeffs,   // [4,1,1024,5]
                            const float* __restrict__ rhs,      // [4,1,1024]
                            const float* __restrict__ iv_rhs,   // [4,1,32]
                            const float* __restrict__ steps0,   // [4,1,31]
                            const float* __restrict__ steps1,   // [4,1,31]
                            float* __restrict__ out)            // u0 [4096] then u [20480]
{
    const int b = blockIdx.x;          // batch
    const int g = threadIdx.x;         // grid node
    const int i0 = g >> 5;
    const int i1 = g & 31;

    __shared__ float xs[GV * KV];      // 20KB solution vector for this batch
    __shared__ float s0[D0V];          // batch-0 steps (only batch 0 enters M)
    __shared__ float s1[D1V];

    if (g < D0V - 1) s0[g] = steps0[g];
    if (g < D1V - 1) s1[g] = steps1[g];
    __syncthreads();

    const bool ep0 = (i0 < D0V - 1), em0 = (i0 > 0);
    const bool ep1 = (i1 < D1V - 1), em1 = (i1 > 0);
    const float hp0 = ep0 ? s0[i0]     : 0.f;   // step of edge (i0 -> i0+1)
    const float hm0 = em0 ? s0[i0 - 1] : 0.f;
    const float hp1 = ep1 ? s1[i1]     : 0.f;
    const float hm1 = em1 ? s1[i1 - 1] : 0.f;

    // ---------------- build 5x5 block B_g from batch-0 data ----------------
    float c0[KV];
#pragma unroll
    for (int k = 0; k < KV; k++) c0[k] = coeffs[g * KV + k];   // batch 0

    float B[KV][KV];
#pragma unroll
    for (int i = 0; i < KV; i++)
#pragma unroll
        for (int j = 0; j < KV; j++)
            B[i][j] = c0[i] * c0[j] + (i == j ? ALPHAP : 0.f);
    if (i0 == 0) B[0][0] += 1.0f;   // initial-condition row on i0==0 edge

    // derivative-row within-block contributions, pairs (s,d,c):
    // (0,1,0) (0,2,1) (1,3,0) (2,4,1)
    // +nbr edge h: B[s][s]+=2w, B[d][d]+=w h^2, B[s][d]+=wh, B[d][s]+=wh
    // -nbr edge h: B[s][s]+=2w, B[d][d]+=w h^2, B[s][d]-=wh, B[d][s]-=wh
    if (ep0) { float h=hp0; B[0][0]+=2*WPEN; B[1][1]+=WPEN*h*h; B[0][1]+=WPEN*h; B[1][0]+=WPEN*h; }
    if (em0) { float h=hm0; B[0][0]+=2*WPEN; B[1][1]+=WPEN*h*h; B[0][1]-=WPEN*h; B[1][0]-=WPEN*h; }
    if (ep1) { float h=hp1; B[0][0]+=2*WPEN; B[2][2]+=WPEN*h*h; B[0][2]+=WPEN*h; B[2][0]+=WPEN*h; }
    if (em1) { float h=hm1; B[0][0]+=2*WPEN; B[2][2]+=WPEN*h*h; B[0][2]-=WPEN*h; B[2][0]-=WPEN*h; }
    if (ep0) { float h=hp0; B[1][1]+=2*WPEN; B[3][3]+=WPEN*h*h; B[1][3]+=WPEN*h; B[3][1]+=WPEN*h; }
    if (em0) { float h=hm0; B[1][1]+=2*WPEN; B[3][3]+=WPEN*h*h; B[1][3]-=WPEN*h; B[3][1]-=WPEN*h; }
    if (ep1) { float h=hp1; B[2][2]+=2*WPEN; B[4][4]+=WPEN*h*h; B[2][4]+=WPEN*h; B[4][2]+=WPEN*h; }
    if (em1) { float h=hm1; B[2][2]+=2*WPEN; B[4][4]+=WPEN*h*h; B[2][4]-=WPEN*h; B[4][2]-=WPEN*h; }

    // ---------------- Cholesky B = L L^T (registers, SPD, no pivot) --------
    float L[KV][KV];
    float id[KV];
#pragma unroll
    for (int j = 0; j < KV; j++) {
        float s = B[j][j];
#pragma unroll
        for (int t = 0; t < KV; t++) if (t < j) s -= L[j][t] * L[j][t];
        float lj = sqrtf(s);
        L[j][j] = lj;
        id[j] = 1.0f / lj;
#pragma unroll
        for (int i = 0; i < KV; i++) if (i > j) {
            float v = B[i][j];
#pragma unroll
            for (int t = 0; t < KV; t++) if (t < j) v -= L[i][t] * L[j][t];
            L[i][j] = v * id[j];
        }
    }

    // ---------------- rhs vector b = -AtPrhs (only eq + iv rows) -----------
    float bv[KV];
    {
        float r = rhs[b * GV + g];
#pragma unroll
        for (int k = 0; k < KV; k++) bv[k] = coeffs[b * (GV * KV) + g * KV + k] * r;
        if (i0 == 0) bv[0] += iv_rhs[b * D1V + i1];
    }

    // in-register 5x5 SPD solve: y <- (L L^T)^{-1} y
    auto solve5 = [&](float y[KV]) {
#pragma unroll
        for (int i = 0; i < KV; i++) {
            float v = y[i];
#pragma unroll
            for (int j = 0; j < KV; j++) if (j < i) v -= L[i][j] * y[j];
            y[i] = v * id[i];
        }
#pragma unroll
        for (int i = KV - 1; i >= 0; i--) {
            float v = y[i];
#pragma unroll
            for (int j = 0; j < KV; j++) if (j > i) v -= L[j][i] * y[j];
            y[i] = v * id[i];
        }
    };

    // x0 = B^{-1} b
    float y[KV];
#pragma unroll
    for (int k = 0; k < KV; k++) y[k] = bv[k];
    solve5(y);
#pragma unroll
    for (int k = 0; k < KV; k++) xs[g * KV + k] = y[k];
    __syncthreads();

    const int gp0 = (g + D1V) * KV, gm0 = (g - D1V) * KV;
    const int gp1 = (g + 1)   * KV, gm1 = (g - 1)   * KV;

    // ---------------- block-Jacobi iterations: x <- B^{-1}(b - E x) --------
    for (int it = 0; it < NITER; it++) {
#pragma unroll
        for (int k = 0; k < KV; k++) y[k] = bv[k];

        // y -= E x  (analytic stencil; E entries from derivative rows, batch-0 steps)
        // pair (s=0,d=1,c=0)
        if (ep0) { float xa = xs[gp0 + 0], xb = xs[gp0 + 1];
                   y[0] += 2*WPEN*xa - WPEN*hp0*xb;  y[1] += WPEN*hp0*xa; }
        if (em0) { float xa = xs[gm0 + 0], xb = xs[gm0 + 1];
                   y[0] += 2*WPEN*xa + WPEN*hm0*xb;  y[1] -= WPEN*hm0*xa; }
        // pair (s=0,d=2,c=1)
        if (ep1) { float xa = xs[gp1 + 0], xb = xs[gp1 + 2];
                   y[0] += 2*WPEN*xa - WPEN*hp1*xb;  y[2] += WPEN*hp1*xa; }
        if (em1) { float xa = xs[gm1 + 0], xb = xs[gm1 + 2];
                   y[0] += 2*WPEN*xa + WPEN*hm1*xb;  y[2] -= WPEN*hm1*xa; }
        // pair (s=1,d=3,c=0)
        if (ep0) { float xa = xs[gp0 + 1], xb = xs[gp0 + 3];
                   y[1] += 2*WPEN*xa - WPEN*hp0*xb;  y[3] += WPEN*hp0*xa; }
        if (em0) { float xa = xs[gm0 + 1], xb = xs[gm0 + 3];
                   y[1] += 2*WPEN*xa + WPEN*hm0*xb;  y[3] -= WPEN*hm0*xa; }
        // pair (s=2,d=4,c=1)
        if (ep1) { float xa = xs[gp1 + 2], xb = xs[gp1 + 4];
                   y[2] += 2*WPEN*xa - WPEN*hp1*xb;  y[4] += WPEN*hp1*xa; }
        if (em1) { float xa = xs[gm1 + 2], xb = xs[gm1 + 4];
                   y[2] += 2*WPEN*xa + WPEN*hm1*xb;  y[4] -= WPEN*hm1*xa; }

        solve5(y);

        __syncthreads();             // all reads of xs done
#pragma unroll
        for (int k = 0; k < KV; k++) xs[g * KV + k] = y[k];
        __syncthreads();             // all writes visible
    }

    // ---------------- outputs: u0 [4,1,1024] then u [4,1,1024,5] -----------
    out[b * GV + g] = y[0];
    float* ou = out + BSV * GV;
#pragma unroll
    for (int k = 0; k < KV; k++) ou[b * (GV * KV) + g * KV + k] = y[k];
}

extern "C" void kernel_launch(void* const* d_in, const int* in_sizes, int n_in,
                              void* d_out, int out_size) {
    const float* coeffs = (const float*)d_in[0];
    const float* rhs    = (const float*)d_in[1];
    const float* iv_rhs = (const float*)d_in[2];
    const float* steps0 = (const float*)d_in[3];
    const float* steps1 = (const float*)d_in[4];
    float* out = (float*)d_out;
    (void)in_sizes; (void)n_in; (void)out_size;

    pde_blockjacobi_kernel<<<BSV, GV>>>(coeffs, rhs, iv_rhs, steps0, steps1, out);
}

// round 2
// speedup vs baseline: 1.5038x; 1.5038x over previous
#include <cuda_runtime.h>

// Problem constants (mirror reference)
#define D0V 32
#define D1V 32
#define GV  1024            // D0*D1
#define KV  5               // n_orders
#define BSV 4               // batches (BS*NID)
#define NITER 8             // rho ~= 0.082 -> rho^8 ~ 2e-9 truncation, fp32-negligible
#define WPEN 0.001f         // 1/DS
#define ALPHAP 0.1f

// Solves M x = b per batch via block-Jacobi:
//   M = B + E,  B = blockdiag of 5x5 node blocks (batch-0 coeffs),
//   E = weak (1e-3 scale) neighbor couplings from derivative constraints.
// Ping-pong x buffers -> single __syncthreads per iteration.
__global__ __launch_bounds__(1024, 1)
void pde_blockjacobi_kernel(const float* __restrict__ coeffs,   // [4,1,1024,5]
                            const float* __restrict__ rhs,      // [4,1,1024]
                            const float* __restrict__ iv_rhs,   // [4,1,32]
                            const float* __restrict__ steps0,   // [4,1,31]
                            const float* __restrict__ steps1,   // [4,1,31]
                            float* __restrict__ out)            // u0 [4096] then u [20480]
{
    const int b = blockIdx.x;          // batch
    const int g = threadIdx.x;         // grid node
    const int i0 = g >> 5;
    const int i1 = g & 31;

    __shared__ float xs[2][GV * KV];   // ping-pong solution buffers (2x20KB)
    __shared__ float s0[D0V];          // batch-0 steps (only batch 0 enters M)
    __shared__ float s1[D1V];

    if (g < D0V - 1) s0[g] = steps0[g];
    if (g < D1V - 1) s1[g] = steps1[g];

    const bool ep0 = (i0 < D0V - 1), em0 = (i0 > 0);
    const bool ep1 = (i1 < D1V - 1), em1 = (i1 > 0);

    // ---------------- batch-b rhs + batch-0 coeffs loads (early) -----------
    float cb[KV], c0[KV];
    const float r = rhs[b * GV + g];
#pragma unroll
    for (int k = 0; k < KV; k++) cb[k] = coeffs[b * (GV * KV) + g * KV + k];
#pragma unroll
    for (int k = 0; k < KV; k++) c0[k] = coeffs[g * KV + k];   // batch 0
    float ivv = (i0 == 0) ? iv_rhs[b * D1V + i1] : 0.f;

    __syncthreads();   // s0/s1 visible

    const float hp0 = ep0 ? s0[i0]     : 0.f;   // step of edge (i0 -> i0+1)
    const float hm0 = em0 ? s0[i0 - 1] : 0.f;
    const float hp1 = ep1 ? s1[i1]     : 0.f;
    const float hm1 = em1 ? s1[i1 - 1] : 0.f;

    // ---------------- build 5x5 block B_g from batch-0 data ----------------
    float B[KV][KV];
#pragma unroll
    for (int i = 0; i < KV; i++)
#pragma unroll
        for (int j = 0; j < KV; j++)
            B[i][j] = c0[i] * c0[j] + (i == j ? ALPHAP : 0.f);
    if (i0 == 0) B[0][0] += 1.0f;   // initial-condition row on i0==0 edge

    // derivative-row within-block contributions, pairs (s,d,c):
    // (0,1,0) (0,2,1) (1,3,0) (2,4,1)
    if (ep0) { float h=hp0; B[0][0]+=2*WPEN; B[1][1]+=WPEN*h*h; B[0][1]+=WPEN*h; B[1][0]+=WPEN*h; }
    if (em0) { float h=hm0; B[0][0]+=2*WPEN; B[1][1]+=WPEN*h*h; B[0][1]-=WPEN*h; B[1][0]-=WPEN*h; }
    if (ep1) { float h=hp1; B[0][0]+=2*WPEN; B[2][2]+=WPEN*h*h; B[0][2]+=WPEN*h; B[2][0]+=WPEN*h; }
    if (em1) { float h=hm1; B[0][0]+=2*WPEN; B[2][2]+=WPEN*h*h; B[0][2]-=WPEN*h; B[2][0]-=WPEN*h; }
    if (ep0) { float h=hp0; B[1][1]+=2*WPEN; B[3][3]+=WPEN*h*h; B[1][3]+=WPEN*h; B[3][1]+=WPEN*h; }
    if (em0) { float h=hm0; B[1][1]+=2*WPEN; B[3][3]+=WPEN*h*h; B[1][3]-=WPEN*h; B[3][1]-=WPEN*h; }
    if (ep1) { float h=hp1; B[2][2]+=2*WPEN; B[4][4]+=WPEN*h*h; B[2][4]+=WPEN*h; B[4][2]+=WPEN*h; }
    if (em1) { float h=hm1; B[2][2]+=2*WPEN; B[4][4]+=WPEN*h*h; B[2][4]-=WPEN*h; B[4][2]-=WPEN*h; }

    // ---------------- Cholesky B = L L^T (registers, SPD, no pivot) --------
    float L[KV][KV];
    float id[KV];
#pragma unroll
    for (int j = 0; j < KV; j++) {
        float s = B[j][j];
#pragma unroll
        for (int t = 0; t < KV; t++) if (t < j) s -= L[j][t] * L[j][t];
        float lj = sqrtf(s);
        L[j][j] = lj;
        id[j] = 1.0f / lj;
#pragma unroll
        for (int i = 0; i < KV; i++) if (i > j) {
            float v = B[i][j];
#pragma unroll
            for (int t = 0; t < KV; t++) if (t < j) v -= L[i][t] * L[j][t];
            L[i][j] = v * id[j];
        }
    }

    // ---------------- rhs vector b = -AtPrhs (only eq + iv rows) -----------
    float bv[KV];
#pragma unroll
    for (int k = 0; k < KV; k++) bv[k] = cb[k] * r;
    bv[0] += ivv;

    // in-register 5x5 SPD solve: y <- (L L^T)^{-1} y
    auto solve5 = [&](float y[KV]) {
#pragma unroll
        for (int i = 0; i < KV; i++) {
            float v = y[i];
#pragma unroll
            for (int j = 0; j < KV; j++) if (j < i) v -= L[i][j] * y[j];
            y[i] = v * id[i];
        }
#pragma unroll
        for (int i = KV - 1; i >= 0; i--) {
            float v = y[i];
#pragma unroll
            for (int j = 0; j < KV; j++) if (j > i) v -= L[j][i] * y[j];
            y[i] = v * id[i];
        }
    };

    // x0 = B^{-1} b  -> buffer 0
    float y[KV];
#pragma unroll
    for (int k = 0; k < KV; k++) y[k] = bv[k];
    solve5(y);
#pragma unroll
    for (int k = 0; k < KV; k++) xs[0][g * KV + k] = y[k];
    __syncthreads();

    const int gp0 = (g + D1V) * KV, gm0 = (g - D1V) * KV;
    const int gp1 = (g + 1)   * KV, gm1 = (g - 1)   * KV;

    // precomputed stencil weights
    const float w2 = 2.0f * WPEN;
    const float wp0 = WPEN * hp0, wm0 = WPEN * hm0;
    const float wp1 = WPEN * hp1, wm1 = WPEN * hm1;

    // ---------------- block-Jacobi: x <- B^{-1}(b - E x), ping-pong --------
    int p = 0;
    for (int it = 0; it < NITER; it++) {
        const float* __restrict__ xc = xs[p];
        float*       __restrict__ xn = xs[p ^ 1];

#pragma unroll
        for (int k = 0; k < KV; k++) y[k] = bv[k];

        // y -= E x  (analytic 4-neighbor stencil, batch-0 steps)
        if (ep0) { float xa = xc[gp0 + 0], xb = xc[gp0 + 1], xd = xc[gp0 + 3];
                   float xe = xc[gp0 + 1]; (void)xe;
                   y[0] += w2*xa - wp0*xb;  y[1] += wp0*xa + w2*xb - wp0*xd;
                   y[3] += wp0*xb; }
        if (em0) { float xa = xc[gm0 + 0], xb = xc[gm0 + 1], xd = xc[gm0 + 3];
                   y[0] += w2*xa + wm0*xb;  y[1] += -wm0*xa + w2*xb + wm0*xd;
                   y[3] += -wm0*xb; }
        if (ep1) { float xa = xc[gp1 + 0], xb = xc[gp1 + 2], xd = xc[gp1 + 4];
                   y[0] += w2*xa - wp1*xb;  y[2] += wp1*xa + w2*xb - wp1*xd;
                   y[4] += wp1*xb; }
        if (em1) { float xa = xc[gm1 + 0], xb = xc[gm1 + 2], xd = xc[gm1 + 4];
                   y[0] += w2*xa + wm1*xb;  y[2] += -wm1*xa + w2*xb + wm1*xd;
                   y[4] += -wm1*xb; }

        solve5(y);

#pragma unroll
        for (int k = 0; k < KV; k++) xn[g * KV + k] = y[k];
        __syncthreads();             // writes to xn visible; reads of xc already done
        p ^= 1;
    }

    // ---------------- outputs: u0 [4,1,1024] then u [4,1,1024,5] -----------
    out[b * GV + g] = y[0];
    float* ou = out + BSV * GV;
#pragma unroll
    for (int k = 0; k < KV; k++) ou[b * (GV * KV) + g * KV + k] = y[k];
}

extern "C" void kernel_launch(void* const* d_in, const int* in_sizes, int n_in,
                              void* d_out, int out_size) {
    const float* coeffs = (const float*)d_in[0];
    const float* rhs    = (const float*)d_in[1];
    const float* iv_rhs = (const float*)d_in[2];
    const float* steps0 = (const float*)d_in[3];
    const float* steps1 = (const float*)d_in[4];
    float* out = (float*)d_out;
    (void)in_sizes; (void)n_in; (void)out_size;

    pde_blockjacobi_kernel<<<BSV, GV>>>(coeffs, rhs, iv_rhs, steps0, steps1, out);
}